// round 11
// baseline (speedup 1.0000x reference)
#include <cuda_runtime.h>
#include <cuda_bf16.h>
#include <cuda_fp16.h>
#include <cstdint>

#define BS   4
#define V    4096
#define NB   32
#define CIN  128
#define COUT 256
#define NROWS (BS*V)        // 16384 distinct (b,u) rows
#define NSAMP (BS*V*NB)     // 524288 samples for BN stats
#define KP    384           // split-K: [hi | lo | hi]
#define KHALF (KP/2)        // 192 per GEMM stage
#define SLD2  (KHALF + 8)   // padded smem stride (200 bf16 -> conflict-free ldmatrix)

// k_prep block-role partition (hist FIRST so it overlaps feat, not tails it)
#define NHIST_BLK 32        // 16384 samples/block, smem-privatized, sliced output
#define NPREPB_BLK 16       // 16 rows/block
#define NZERO_BLK 1
#define NFEAT_BLK 2048      // 8 rows/block (8 warps)
#define PREP_GRID (NHIST_BLK + NPREPB_BLK + NZERO_BLK + NFEAT_BLK)

// -------- scratch (device globals; no allocations allowed) --------
__device__ __align__(16) __nv_bfloat16 g_A2[NROWS * KP];   // 12.6 MB
__device__ __align__(16) __nv_bfloat16 g_B2[COUT * KP];    // 192 KB
__device__ __align__(16) __half g_Zh[NROWS * COUT];        // 8 MB  raw z (fp16)
__device__ int   g_cnt8[8 * NROWS];                        // sliced histogram (no zeroing)
__device__ float g_sum[COUT], g_sq[COUT];

static __device__ __forceinline__ uint32_t smem_u32(const void* p) {
    uint32_t a;
    asm("{ .reg .u64 t; cvta.to.shared.u64 t, %1; cvt.u32.u64 %0, t; }"
        : "=r"(a) : "l"(p));
    return a;
}
static __device__ __forceinline__ void ldsm_x4(uint32_t* r, uint32_t addr) {
    asm volatile("ldmatrix.sync.aligned.m8n8.x4.shared.b16 {%0,%1,%2,%3}, [%4];"
                 : "=r"(r[0]), "=r"(r[1]), "=r"(r[2]), "=r"(r[3]) : "r"(addr));
}
static __device__ __forceinline__ void mma_bf16(float* c, const uint32_t* a,
                                                uint32_t b0, uint32_t b1) {
    asm volatile(
        "mma.sync.aligned.m16n8k16.row.col.f32.bf16.bf16.f32 "
        "{%0,%1,%2,%3}, {%4,%5,%6,%7}, {%8,%9}, {%0,%1,%2,%3};"
        : "+f"(c[0]), "+f"(c[1]), "+f"(c[2]), "+f"(c[3])
        : "r"(a[0]), "r"(a[1]), "r"(a[2]), "r"(a[3]), "r"(b0), "r"(b1));
}
static __device__ __forceinline__ uint32_t h2u(__half2 h) {
    return *reinterpret_cast<uint32_t*>(&h);
}
static __device__ __forceinline__ __half2 u2h(uint32_t u) {
    return *reinterpret_cast<__half2*>(&u);
}

// -------- K1: fused prep: hist (first!) + prepB + zero + feat ---------------
__global__ __launch_bounds__(256) void k_prep(const float* __restrict__ fmap,
                                              const float* __restrict__ Wm,
                                              const int* __restrict__ idx) {
    int blk = blockIdx.x;
    int tid = threadIdx.x;

    if (blk < NHIST_BLK) {
        // ---- hist: smem-privatized histogram, slice-private output (no atomics) ----
        __shared__ int scnt[V];
        int batch = blk >> 3, s = blk & 7;
        #pragma unroll
        for (int j = tid; j < V; j += 256) scnt[j] = 0;
        __syncthreads();
        const int4* src = (const int4*)(idx + (size_t)batch * (V * NB) + s * 16384);
        #pragma unroll 4
        for (int it = 0; it < 16; it++) {
            int4 v = src[it * 256 + tid];
            atomicAdd(&scnt[v.x], 1);
            atomicAdd(&scnt[v.y], 1);
            atomicAdd(&scnt[v.z], 1);
            atomicAdd(&scnt[v.w], 1);
        }
        __syncthreads();
        for (int j = tid; j < V; j += 256)
            g_cnt8[s * NROWS + (batch << 12) + j] = scnt[j];
    } else if (blk < NHIST_BLK + NPREPB_BLK) {
        // ---- prepB: B' rows = [hi(W) | hi(W) | lo(W)] ----
        int base = (blk - NHIST_BLK) * 16;       // 16 rows per block
        for (int i = tid; i < 16 * CIN; i += 256) {
            int n = base + (i >> 7);
            int k = i & 127;
            float w = Wm[(size_t)n * CIN + k];
            __nv_bfloat16 h = __float2bfloat16_rn(w);
            __nv_bfloat16 l = __float2bfloat16_rn(w - __bfloat162float(h));
            __nv_bfloat16* dst = g_B2 + (size_t)n * KP;
            dst[k] = h; dst[k + 128] = h; dst[k + 256] = l;
        }
    } else if (blk < NHIST_BLK + NPREPB_BLK + NZERO_BLK) {
        // ---- zero BN accumulators (replay-deterministic) ----
        g_sum[tid] = 0.0f;
        g_sq[tid]  = 0.0f;
    } else {
        // ---- feat: A' rows = [hi(F) | lo(F) | hi(F)], F = [fmap, ||fmap||] ----
        int warp = (blk - NHIST_BLK - NPREPB_BLK - NZERO_BLK) * 8 + (tid >> 5);
        int lane = tid & 31;
        const float* src = fmap + (size_t)warp * (CIN - 1);
        float v0 = src[lane];
        float v1 = src[lane + 32];
        float v2 = src[lane + 64];
        float v3 = (lane < 31) ? src[lane + 96] : 0.0f;
        float ss = v0*v0 + v1*v1 + v2*v2 + v3*v3;
        #pragma unroll
        for (int o = 16; o; o >>= 1) ss += __shfl_xor_sync(0xffffffffu, ss, o);
        if (lane == 31) v3 = sqrtf(ss);      // channel 127 = L2 distance
        __nv_bfloat16* dst = g_A2 + (size_t)warp * KP;
        float vv[4] = {v0, v1, v2, v3};
        #pragma unroll
        for (int q = 0; q < 4; q++) {
            int c = lane + q * 32;
            __nv_bfloat16 h = __float2bfloat16_rn(vv[q]);
            __nv_bfloat16 l = __float2bfloat16_rn(vv[q] - __bfloat162float(h));
            dst[c] = h; dst[c + 128] = l; dst[c + 256] = h;
        }
    }
}

// -------- K2: HMMA GEMM  z = A' @ B'^T + bias -> fp16 Zh, fused BN stats ----
// CTA 128x128; K'=384 in TWO stages of 192 (smem 102 KB -> 2 CTAs/SM, 1 wave).
__global__ __launch_bounds__(256, 2) void k_gemm_mma(const float* __restrict__ bias) {
    extern __shared__ __nv_bfloat16 sm[];
    __nv_bfloat16* As = sm;                  // [128][SLD2]
    __nv_bfloat16* Bs = sm + 128 * SLD2;     // [128][SLD2]
    int tid = threadIdx.x, wid = tid >> 5, lane = tid & 31;
    int mbase = blockIdx.x * 128, nbase = blockIdx.y * 128;

    int warp_m = (wid >> 2) * 64;            // 2 warp-rows
    int warp_n = (wid & 3) * 32;             // 4 warp-cols
    uint32_t sb = smem_u32(sm);
    uint32_t aaddr = sb + (uint32_t)(((warp_m + (lane & 15)) * SLD2 + (lane >> 4) * 8) * 2);
    uint32_t baddr = sb + (uint32_t)((128 * SLD2
                     + (warp_n + ((lane >> 4) & 1) * 8 + (lane & 7)) * SLD2
                     + ((lane >> 3) & 1) * 8) * 2);

    float acc[4][4][4];
    #pragma unroll
    for (int mi = 0; mi < 4; mi++)
        #pragma unroll
        for (int ni = 0; ni < 4; ni++)
            #pragma unroll
            for (int q = 0; q < 4; q++) acc[mi][ni][q] = 0.0f;

    #pragma unroll 1
    for (int s = 0; s < 2; s++) {
        if (s) __syncthreads();              // prior stage's mma reads complete
        const uint4* Ag = (const uint4*)(g_A2 + (size_t)mbase * KP + s * KHALF);
        const uint4* Bg = (const uint4*)(g_B2 + (size_t)nbase * KP + s * KHALF);
        #pragma unroll
        for (int i = tid; i < 128 * 24; i += 256) {
            int r = i / 24, c = i % 24;
            *(uint4*)&As[r * SLD2 + c * 8] = Ag[r * 48 + c];   // 48 = KP/8 row stride
            *(uint4*)&Bs[r * SLD2 + c * 8] = Bg[r * 48 + c];
        }
        __syncthreads();

        #pragma unroll 2
        for (int ks = 0; ks < KHALF / 16; ks++) {
            uint32_t koff = (uint32_t)(ks * 16 * 2);
            uint32_t a[4][4], b[2][4];
            #pragma unroll
            for (int mi = 0; mi < 4; mi++)
                ldsm_x4(a[mi], aaddr + (uint32_t)(mi * 16 * SLD2 * 2) + koff);
            #pragma unroll
            for (int nj = 0; nj < 2; nj++)
                ldsm_x4(b[nj], baddr + (uint32_t)(nj * 16 * SLD2 * 2) + koff);
            #pragma unroll
            for (int mi = 0; mi < 4; mi++)
                #pragma unroll
                for (int ni = 0; ni < 4; ni++)
                    mma_bf16(acc[mi][ni], a[mi],
                             b[ni >> 1][(ni & 1) * 2], b[ni >> 1][(ni & 1) * 2 + 1]);
        }
    }

    // ---- epilogue: tiles dead; reuse smem for per-CTA stats ----
    __syncthreads();
    float* ssum = (float*)sm;        // [128]
    float* ssq  = ssum + 128;        // [128]
    if (tid < 128) ssum[tid] = 0.0f;
    else if (tid < 256) ssq[tid - 128] = 0.0f;
    __syncthreads();

    int r0 = lane >> 2, c0 = (lane & 3) * 2;
    float wlo[4], whi[4];
    #pragma unroll
    for (int mi = 0; mi < 4; mi++) {
        int rowA = mbase + warp_m + mi * 16 + r0;
        int lo = 0, hi = 0;
        #pragma unroll
        for (int s = 0; s < 8; s++) {
            lo += __ldg(&g_cnt8[s * NROWS + rowA]);
            hi += __ldg(&g_cnt8[s * NROWS + rowA + 8]);
        }
        wlo[mi] = (float)lo; whi[mi] = (float)hi;
    }
    #pragma unroll
    for (int ni = 0; ni < 4; ni++) {
        int coll = warp_n + ni * 8 + c0;             // 0..127 local col
        int col  = nbase + coll;
        float bx = __ldg(&bias[col]), by = __ldg(&bias[col + 1]);
        float sx = 0.f, qx = 0.f, sy = 0.f, qy = 0.f;
        #pragma unroll
        for (int mi = 0; mi < 4; mi++) {
            int rowA = mbase + warp_m + mi * 16 + r0;
            float v0 = acc[mi][ni][0] + bx, v1 = acc[mi][ni][1] + by;
            float v2 = acc[mi][ni][2] + bx, v3 = acc[mi][ni][3] + by;
            __half2 h0 = __floats2half2_rn(v0, v1);
            __half2 h1 = __floats2half2_rn(v2, v3);
            *(__half2*)&g_Zh[(size_t)rowA * COUT + col] = h0;
            *(__half2*)&g_Zh[(size_t)(rowA + 8) * COUT + col] = h1;
            sx = fmaf(wlo[mi], v0, sx); qx = fmaf(wlo[mi] * v0, v0, qx);
            sx = fmaf(whi[mi], v2, sx); qx = fmaf(whi[mi] * v2, v2, qx);
            sy = fmaf(wlo[mi], v1, sy); qy = fmaf(wlo[mi] * v1, v1, qy);
            sy = fmaf(whi[mi], v3, sy); qy = fmaf(whi[mi] * v3, v3, qy);
        }
        atomicAdd(&ssum[coll], sx);     atomicAdd(&ssq[coll], qx);
        atomicAdd(&ssum[coll + 1], sy); atomicAdd(&ssq[coll + 1], qy);
    }
    __syncthreads();
    if (tid < 128)      atomicAdd(&g_sum[nbase + tid], ssum[tid]);
    else if (tid < 256) atomicAdd(&g_sq[nbase + tid - 128], ssq[tid - 128]);
}

// -------- K3: fused BN + theta * relu(zn), max over neighbors, half2 math ---
// 32 threads per row (one warp), 8 channels/thread; 4 rows per 128-thread block.
// theta relu dropped: zn >= 0 and acc starts at 0, so negative-theta candidates
// can never win the max — mathematically identical to relu(theta)*zn.
__global__ __launch_bounds__(128, 9) void k_final(const int* __restrict__ idx,
                                                  const float* __restrict__ verts,
                                                  const float* __restrict__ dirs,
                                                  const float* __restrict__ gamma,
                                                  const float* __restrict__ beta,
                                                  float* __restrict__ out) {
    __shared__ uint4 sh[4][NB];      // per neighbor: wx2, wy2, wz2 (half2), byte-offset
    int r    = threadIdx.x >> 5;     // row within block
    int lane = threadIdx.x & 31;     // = neighbor id (setup) = channel group (main)
    int row  = blockIdx.x * 4 + r;
    int b    = row >> 12;

    // ---- setup: this warp fills its own row's neighbor table ----
    {
        int u = idx[(size_t)row * NB + lane];
        const float* nv = verts + (size_t)((b << 12) + u) * 3;
        const float* cv = verts + (size_t)row * 3;
        float dx = nv[0] - cv[0], dy = nv[1] - cv[1], dz = nv[2] - cv[2];
        float nrm = sqrtf(dx*dx + dy*dy + dz*dz);
        float inv = 1.0f / fmaxf(nrm, 1e-12f);
        uint4 w;
        w.x = h2u(__float2half2_rn(fmaf(dx*inv, 0.5f, 0.5f)));
        w.y = h2u(__float2half2_rn(fmaf(dy*inv, 0.5f, 0.5f)));
        w.z = h2u(__float2half2_rn(fmaf(dz*inv, 0.5f, 0.5f)));
        w.w = (uint32_t)(((b << 12) + u) * COUT * 2);   // byte offset into g_Zh
        sh[r][lane] = w;
    }

    // ---- per-thread channel constants (8 channels: c0..c0+7) ----
    int c0 = lane * 8;
    uint32_t s1h[4], s2h[4], s3h[4], r0h[4], ah[4], dh[4];
    {
        const float invN = 1.0f / (float)NSAMP;
        #pragma unroll
        for (int j = 0; j < 4; j++) {
            int c = c0 + j * 2;
            float d0a = __ldg(&dirs[c]),            d0b = __ldg(&dirs[c + 1]);
            float d1a = __ldg(&dirs[COUT + c]),     d1b = __ldg(&dirs[COUT + c + 1]);
            float d2a = __ldg(&dirs[2*COUT + c]),   d2b = __ldg(&dirs[2*COUT + c + 1]);
            float d3a = __ldg(&dirs[3*COUT + c]),   d3b = __ldg(&dirs[3*COUT + c + 1]);
            r0h[j] = h2u(__floats2half2_rn(d0a, d0b));
            s1h[j] = h2u(__floats2half2_rn(d1a - d0a, d1b - d0b));
            s2h[j] = h2u(__floats2half2_rn(d2a - d0a, d2b - d0b));
            s3h[j] = h2u(__floats2half2_rn(d3a - d0a, d3b - d0b));
            float ma = __ldg(&g_sum[c]) * invN,     mb = __ldg(&g_sum[c+1]) * invN;
            float va = fmaxf(__ldg(&g_sq[c]) * invN - ma * ma, 0.0f);
            float vb = fmaxf(__ldg(&g_sq[c+1]) * invN - mb * mb, 0.0f);
            float aa = __ldg(&gamma[c])   / sqrtf(va + 1e-5f);
            float ab = __ldg(&gamma[c+1]) / sqrtf(vb + 1e-5f);
            ah[j] = h2u(__floats2half2_rn(aa, ab));
            dh[j] = h2u(__floats2half2_rn(__ldg(&beta[c])   - ma * aa,
                                          __ldg(&beta[c+1]) - mb * ab));
        }
    }
    __syncwarp();

    const __half2 zero2 = __float2half2_rn(0.0f);
    __half2 acc[4] = {zero2, zero2, zero2, zero2};
    const char* zb = (const char*)g_Zh + (size_t)(lane * 16);

    #pragma unroll
    for (int n = 0; n < NB; n++) {
        uint4 w = sh[r][n];
        __half2 wx = u2h(w.x), wy = u2h(w.y), wz = u2h(w.z);
        uint4 p = *(const uint4*)(zb + w.w);
        uint32_t pv[4] = {p.x, p.y, p.z, p.w};
        #pragma unroll
        for (int j = 0; j < 4; j++) {
            __half2 zn = __hmax2(__hfma2(u2h(pv[j]), u2h(ah[j]), u2h(dh[j])), zero2);
            __half2 th = __hfma2(wz, u2h(s3h[j]), u2h(r0h[j]));
            th = __hfma2(wy, u2h(s2h[j]), th);
            th = __hfma2(wx, u2h(s1h[j]), th);
            acc[j] = __hmax2(acc[j], __hmul2(zn, th));
        }
    }

    float* orow = out + (size_t)row * COUT + c0;
    float2 f0 = __half22float2(acc[0]);
    float2 f1 = __half22float2(acc[1]);
    float2 f2 = __half22float2(acc[2]);
    float2 f3 = __half22float2(acc[3]);
    *(float4*)&orow[0] = make_float4(f0.x, f0.y, f1.x, f1.y);
    *(float4*)&orow[4] = make_float4(f2.x, f2.y, f3.x, f3.y);
}

extern "C" void kernel_launch(void* const* d_in, const int* in_sizes, int n_in,
                              void* d_out, int out_size) {
    const int*   idx   = (const int*)d_in[0];
    const float* verts = (const float*)d_in[1];
    const float* fmap  = (const float*)d_in[2];
    const float* dirs  = (const float*)d_in[3];
    const float* Wm    = (const float*)d_in[4];
    const float* bias  = (const float*)d_in[5];
    const float* gamma = (const float*)d_in[6];
    const float* beta  = (const float*)d_in[7];
    float* out = (float*)d_out;

    k_prep<<<PREP_GRID, 256>>>(fmap, Wm, idx);

    const int smem = 2 * 128 * SLD2 * (int)sizeof(__nv_bfloat16);   // 102400 B
    cudaFuncSetAttribute(k_gemm_mma, cudaFuncAttributeMaxDynamicSharedMemorySize, smem);
    k_gemm_mma<<<dim3(NROWS / 128, COUT / 128), 256, smem>>>(bias);

    k_final<<<NROWS / 4, 128>>>(idx, verts, dirs, gamma, beta, out);
}

// round 12
// speedup vs baseline: 1.1199x; 1.1199x over previous
#include <cuda_runtime.h>
#include <cuda_bf16.h>
#include <cuda_fp16.h>
#include <cstdint>

#define BS   4
#define V    4096
#define NB   32
#define CIN  128
#define COUT 256
#define NROWS (BS*V)        // 16384 distinct (b,u) rows
#define NSAMP (BS*V*NB)     // 524288 samples for BN stats
#define KP    384           // logical split-K: A'=[hi|lo|hi], B'=[hi|hi|lo]
#define KST   256           // stored K: [hi|lo] only; GEMM remaps duplicate blocks
#define KHALF (KP/2)        // 192 per GEMM stage
#define SLD2  (KHALF + 8)   // padded smem stride (200 bf16 -> conflict-free ldmatrix)

// k_prep block-role partition (hist FIRST so it overlaps feat, not tails it)
#define NHIST_BLK 32        // 16384 samples/block, smem-privatized, sliced output
#define NPREPB_BLK 16       // 16 rows/block
#define NZERO_BLK 1
#define NFEAT_BLK 2048      // 8 rows/block (8 warps)
#define PREP_GRID (NHIST_BLK + NPREPB_BLK + NZERO_BLK + NFEAT_BLK)

// -------- scratch (device globals; no allocations allowed) --------
__device__ __align__(16) __nv_bfloat16 g_A2[NROWS * KST];  // 8.4 MB [hi|lo]
__device__ __align__(16) __nv_bfloat16 g_B2[COUT * KST];   // 128 KB [hi|lo]
__device__ __align__(16) __half g_Zh[NROWS * COUT];        // 8 MB  z -> relu(BN(z)) fp16
__device__ int   g_cnt8[8 * NROWS];                        // sliced histogram (no zeroing)
__device__ float g_sum[COUT], g_sq[COUT];

static __device__ __forceinline__ uint32_t smem_u32(const void* p) {
    uint32_t a;
    asm("{ .reg .u64 t; cvta.to.shared.u64 t, %1; cvt.u32.u64 %0, t; }"
        : "=r"(a) : "l"(p));
    return a;
}
static __device__ __forceinline__ void ldsm_x4(uint32_t* r, uint32_t addr) {
    asm volatile("ldmatrix.sync.aligned.m8n8.x4.shared.b16 {%0,%1,%2,%3}, [%4];"
                 : "=r"(r[0]), "=r"(r[1]), "=r"(r[2]), "=r"(r[3]) : "r"(addr));
}
static __device__ __forceinline__ void mma_bf16(float* c, const uint32_t* a,
                                                uint32_t b0, uint32_t b1) {
    asm volatile(
        "mma.sync.aligned.m16n8k16.row.col.f32.bf16.bf16.f32 "
        "{%0,%1,%2,%3}, {%4,%5,%6,%7}, {%8,%9}, {%0,%1,%2,%3};"
        : "+f"(c[0]), "+f"(c[1]), "+f"(c[2]), "+f"(c[3])
        : "r"(a[0]), "r"(a[1]), "r"(a[2]), "r"(a[3]), "r"(b0), "r"(b1));
}
static __device__ __forceinline__ uint32_t h2u(__half2 h) {
    return *reinterpret_cast<uint32_t*>(&h);
}
static __device__ __forceinline__ __half2 u2h(uint32_t u) {
    return *reinterpret_cast<__half2*>(&u);
}

// -------- K1: fused prep: hist (first!) + prepB + zero + feat ---------------
__global__ __launch_bounds__(256) void k_prep(const float* __restrict__ fmap,
                                              const float* __restrict__ Wm,
                                              const int* __restrict__ idx) {
    int blk = blockIdx.x;
    int tid = threadIdx.x;

    if (blk < NHIST_BLK) {
        // ---- hist: smem-privatized histogram, slice-private output (no atomics) ----
        __shared__ int scnt[V];
        int batch = blk >> 3, s = blk & 7;
        #pragma unroll
        for (int j = tid; j < V; j += 256) scnt[j] = 0;
        __syncthreads();
        const int4* src = (const int4*)(idx + (size_t)batch * (V * NB) + s * 16384);
        #pragma unroll 4
        for (int it = 0; it < 16; it++) {
            int4 v = src[it * 256 + tid];
            atomicAdd(&scnt[v.x], 1);
            atomicAdd(&scnt[v.y], 1);
            atomicAdd(&scnt[v.z], 1);
            atomicAdd(&scnt[v.w], 1);
        }
        __syncthreads();
        for (int j = tid; j < V; j += 256)
            g_cnt8[s * NROWS + (batch << 12) + j] = scnt[j];
    } else if (blk < NHIST_BLK + NPREPB_BLK) {
        // ---- prepB: B' rows = [hi(W) | lo(W)] (dup hi handled by GEMM remap) ----
        int base = (blk - NHIST_BLK) * 16;       // 16 rows per block
        for (int i = tid; i < 16 * CIN; i += 256) {
            int n = base + (i >> 7);
            int k = i & 127;
            float w = Wm[(size_t)n * CIN + k];
            __nv_bfloat16 h = __float2bfloat16_rn(w);
            __nv_bfloat16 l = __float2bfloat16_rn(w - __bfloat162float(h));
            __nv_bfloat16* dst = g_B2 + (size_t)n * KST;
            dst[k] = h; dst[k + 128] = l;
        }
    } else if (blk < NHIST_BLK + NPREPB_BLK + NZERO_BLK) {
        // ---- zero BN accumulators (replay-deterministic) ----
        g_sum[tid] = 0.0f;
        g_sq[tid]  = 0.0f;
    } else {
        // ---- feat: A' rows = [hi(F) | lo(F)], F = [fmap, ||fmap||] ----
        int warp = (blk - NHIST_BLK - NPREPB_BLK - NZERO_BLK) * 8 + (tid >> 5);
        int lane = tid & 31;
        const float* src = fmap + (size_t)warp * (CIN - 1);
        float v0 = src[lane];
        float v1 = src[lane + 32];
        float v2 = src[lane + 64];
        float v3 = (lane < 31) ? src[lane + 96] : 0.0f;
        float ss = v0*v0 + v1*v1 + v2*v2 + v3*v3;
        #pragma unroll
        for (int o = 16; o; o >>= 1) ss += __shfl_xor_sync(0xffffffffu, ss, o);
        if (lane == 31) v3 = sqrtf(ss);      // channel 127 = L2 distance
        __nv_bfloat16* dst = g_A2 + (size_t)warp * KST;
        float vv[4] = {v0, v1, v2, v3};
        #pragma unroll
        for (int q = 0; q < 4; q++) {
            int c = lane + q * 32;
            __nv_bfloat16 h = __float2bfloat16_rn(vv[q]);
            __nv_bfloat16 l = __float2bfloat16_rn(vv[q] - __bfloat162float(h));
            dst[c] = h; dst[c + 128] = l;
        }
    }
}

// -------- K2: HMMA GEMM  z = A' @ B'^T + bias -> fp16 Zh, fused BN stats ----
// CTA 128x128; logical K'=384 in TWO stages of 192 (smem 102 KB, 2 CTAs/SM).
// Gmem chunk remap reconstructs A'=[hi|lo|hi], B'=[hi|hi|lo] from [hi|lo].
__global__ __launch_bounds__(256, 2) void k_gemm_mma(const float* __restrict__ bias) {
    extern __shared__ __nv_bfloat16 sm[];
    __nv_bfloat16* As = sm;                  // [128][SLD2]
    __nv_bfloat16* Bs = sm + 128 * SLD2;     // [128][SLD2]
    int tid = threadIdx.x, wid = tid >> 5, lane = tid & 31;
    int mbase = blockIdx.x * 128, nbase = blockIdx.y * 128;

    int warp_m = (wid >> 2) * 64;            // 2 warp-rows
    int warp_n = (wid & 3) * 32;             // 4 warp-cols
    uint32_t sb = smem_u32(sm);
    uint32_t aaddr = sb + (uint32_t)(((warp_m + (lane & 15)) * SLD2 + (lane >> 4) * 8) * 2);
    uint32_t baddr = sb + (uint32_t)((128 * SLD2
                     + (warp_n + ((lane >> 4) & 1) * 8 + (lane & 7)) * SLD2
                     + ((lane >> 3) & 1) * 8) * 2);

    float acc[4][4][4];
    #pragma unroll
    for (int mi = 0; mi < 4; mi++)
        #pragma unroll
        for (int ni = 0; ni < 4; ni++)
            #pragma unroll
            for (int q = 0; q < 4; q++) acc[mi][ni][q] = 0.0f;

    #pragma unroll 1
    for (int s = 0; s < 2; s++) {
        if (s) __syncthreads();              // prior stage's mma reads complete
        const uint4* Ag = (const uint4*)(g_A2 + (size_t)mbase * KST);
        const uint4* Bg = (const uint4*)(g_B2 + (size_t)nbase * KST);
        #pragma unroll
        for (int i = tid; i < 128 * 24; i += 256) {
            int r = i / 24, c = i % 24;
            int g  = s * 24 + c;                   // logical k-chunk 0..47
            int ga = (g < 32) ? g : g - 32;        // A' = [hi|lo|hi]
            int gb = (g < 16) ? g : g - 16;        // B' = [hi|hi|lo]
            *(uint4*)&As[r * SLD2 + c * 8] = Ag[r * 32 + ga];  // 32 = KST/8 stride
            *(uint4*)&Bs[r * SLD2 + c * 8] = Bg[r * 32 + gb];
        }
        __syncthreads();

        #pragma unroll 2
        for (int ks = 0; ks < KHALF / 16; ks++) {
            uint32_t koff = (uint32_t)(ks * 16 * 2);
            uint32_t a[4][4], b[2][4];
            #pragma unroll
            for (int mi = 0; mi < 4; mi++)
                ldsm_x4(a[mi], aaddr + (uint32_t)(mi * 16 * SLD2 * 2) + koff);
            #pragma unroll
            for (int nj = 0; nj < 2; nj++)
                ldsm_x4(b[nj], baddr + (uint32_t)(nj * 16 * SLD2 * 2) + koff);
            #pragma unroll
            for (int mi = 0; mi < 4; mi++)
                #pragma unroll
                for (int ni = 0; ni < 4; ni++)
                    mma_bf16(acc[mi][ni], a[mi],
                             b[ni >> 1][(ni & 1) * 2], b[ni >> 1][(ni & 1) * 2 + 1]);
        }
    }

    // ---- epilogue: tiles dead; reuse smem for per-CTA stats ----
    __syncthreads();
    float* ssum = (float*)sm;        // [128]
    float* ssq  = ssum + 128;        // [128]
    if (tid < 128) ssum[tid] = 0.0f;
    else if (tid < 256) ssq[tid - 128] = 0.0f;
    __syncthreads();

    int r0 = lane >> 2, c0 = (lane & 3) * 2;
    float wlo[4], whi[4];
    #pragma unroll
    for (int mi = 0; mi < 4; mi++) {
        int rowA = mbase + warp_m + mi * 16 + r0;
        int lo = 0, hi = 0;
        #pragma unroll
        for (int s = 0; s < 8; s++) {
            lo += __ldg(&g_cnt8[s * NROWS + rowA]);
            hi += __ldg(&g_cnt8[s * NROWS + rowA + 8]);
        }
        wlo[mi] = (float)lo; whi[mi] = (float)hi;
    }
    #pragma unroll
    for (int ni = 0; ni < 4; ni++) {
        int coll = warp_n + ni * 8 + c0;             // 0..127 local col
        int col  = nbase + coll;
        float bx = __ldg(&bias[col]), by = __ldg(&bias[col + 1]);
        float sx = 0.f, qx = 0.f, sy = 0.f, qy = 0.f;
        #pragma unroll
        for (int mi = 0; mi < 4; mi++) {
            int rowA = mbase + warp_m + mi * 16 + r0;
            float v0 = acc[mi][ni][0] + bx, v1 = acc[mi][ni][1] + by;
            float v2 = acc[mi][ni][2] + bx, v3 = acc[mi][ni][3] + by;
            __half2 h0 = __floats2half2_rn(v0, v1);
            __half2 h1 = __floats2half2_rn(v2, v3);
            *(__half2*)&g_Zh[(size_t)rowA * COUT + col] = h0;
            *(__half2*)&g_Zh[(size_t)(rowA + 8) * COUT + col] = h1;
            sx = fmaf(wlo[mi], v0, sx); qx = fmaf(wlo[mi] * v0, v0, qx);
            sx = fmaf(whi[mi], v2, sx); qx = fmaf(whi[mi] * v2, v2, qx);
            sy = fmaf(wlo[mi], v1, sy); qy = fmaf(wlo[mi] * v1, v1, qy);
            sy = fmaf(whi[mi], v3, sy); qy = fmaf(whi[mi] * v3, v3, qy);
        }
        atomicAdd(&ssum[coll], sx);     atomicAdd(&ssq[coll], qx);
        atomicAdd(&ssum[coll + 1], sy); atomicAdd(&ssq[coll + 1], qy);
    }
    __syncthreads();
    if (tid < 128)      atomicAdd(&g_sum[nbase + tid], ssum[tid]);
    else if (tid < 256) atomicAdd(&g_sq[nbase + tid - 128], ssq[tid - 128]);
}

// -------- K3: Zh <- fp16(relu(BN(Zh))) in place, fp32 intermediate ----------
__global__ __launch_bounds__(256) void k_norm(const float* __restrict__ gamma,
                                              const float* __restrict__ beta) {
    __shared__ float sa[COUT], sd[COUT];
    int t = threadIdx.x;
    {
        const float invN = 1.0f / (float)NSAMP;
        float mean = g_sum[t] * invN;
        float var  = fmaxf(g_sq[t] * invN - mean * mean, 0.0f);
        float a    = gamma[t] / sqrtf(var + 1e-5f);
        sa[t] = a;
        sd[t] = beta[t] - mean * a;
    }
    __syncthreads();

    int i = blockIdx.x * 256 + t;            // uint4 index: 8 halves
    int c0 = (i * 8) & (COUT - 1);
    uint4 p = ((const uint4*)g_Zh)[i];
    uint32_t pv[4] = {p.x, p.y, p.z, p.w};
    #pragma unroll
    for (int j = 0; j < 4; j++) {
        float2 f = __half22float2(u2h(pv[j]));
        int c = c0 + j * 2;
        f.x = fmaxf(fmaf(f.x, sa[c],     sd[c]),     0.0f);
        f.y = fmaxf(fmaf(f.y, sa[c + 1], sd[c + 1]), 0.0f);
        pv[j] = h2u(__floats2half2_rn(f.x, f.y));
    }
    ((uint4*)g_Zh)[i] = make_uint4(pv[0], pv[1], pv[2], pv[3]);
}

// -------- K4: theta * zn, max over neighbors, half2 math --------------------
// 32 threads per row (one warp), 8 channels/thread; 4 rows per 128-thread block.
// theta relu dropped: zn >= 0 and acc starts at 0, so negative-theta candidates
// can never win the max — mathematically identical to relu(theta)*zn.
__global__ __launch_bounds__(128, 9) void k_final(const int* __restrict__ idx,
                                                  const float* __restrict__ verts,
                                                  const float* __restrict__ dirs,
                                                  float* __restrict__ out) {
    __shared__ uint4 sh[4][NB];      // per neighbor: wx2, wy2, wz2 (half2), byte-offset
    int r    = threadIdx.x >> 5;     // row within block
    int lane = threadIdx.x & 31;     // = neighbor id (setup) = channel group (main)
    int row  = blockIdx.x * 4 + r;
    int b    = row >> 12;

    // ---- setup: this warp fills its own row's neighbor table ----
    {
        int u = idx[(size_t)row * NB + lane];
        const float* nv = verts + (size_t)((b << 12) + u) * 3;
        const float* cv = verts + (size_t)row * 3;
        float dx = nv[0] - cv[0], dy = nv[1] - cv[1], dz = nv[2] - cv[2];
        float nrm = sqrtf(dx*dx + dy*dy + dz*dz);
        float inv = 1.0f / fmaxf(nrm, 1e-12f);
        uint4 w;
        w.x = h2u(__float2half2_rn(fmaf(dx*inv, 0.5f, 0.5f)));
        w.y = h2u(__float2half2_rn(fmaf(dy*inv, 0.5f, 0.5f)));
        w.z = h2u(__float2half2_rn(fmaf(dz*inv, 0.5f, 0.5f)));
        w.w = (uint32_t)(((b << 12) + u) * COUT * 2);   // byte offset into g_Zh
        sh[r][lane] = w;
    }

    // ---- per-thread channel constants (8 channels: c0..c0+7) ----
    int c0 = lane * 8;
    uint32_t s1h[4], s2h[4], s3h[4], r0h[4];
    #pragma unroll
    for (int j = 0; j < 4; j++) {
        int c = c0 + j * 2;
        float d0a = __ldg(&dirs[c]),            d0b = __ldg(&dirs[c + 1]);
        float d1a = __ldg(&dirs[COUT + c]),     d1b = __ldg(&dirs[COUT + c + 1]);
        float d2a = __ldg(&dirs[2*COUT + c]),   d2b = __ldg(&dirs[2*COUT + c + 1]);
        float d3a = __ldg(&dirs[3*COUT + c]),   d3b = __ldg(&dirs[3*COUT + c + 1]);
        r0h[j] = h2u(__floats2half2_rn(d0a, d0b));
        s1h[j] = h2u(__floats2half2_rn(d1a - d0a, d1b - d0b));
        s2h[j] = h2u(__floats2half2_rn(d2a - d0a, d2b - d0b));
        s3h[j] = h2u(__floats2half2_rn(d3a - d0a, d3b - d0b));
    }
    __syncwarp();

    const __half2 zero2 = __float2half2_rn(0.0f);
    __half2 acc[4] = {zero2, zero2, zero2, zero2};
    const char* zb = (const char*)g_Zh + (size_t)(lane * 16);

    #pragma unroll
    for (int n = 0; n < NB; n++) {
        uint4 w = sh[r][n];
        __half2 wx = u2h(w.x), wy = u2h(w.y), wz = u2h(w.z);
        uint4 p = *(const uint4*)(zb + w.w);
        uint32_t pv[4] = {p.x, p.y, p.z, p.w};
        #pragma unroll
        for (int j = 0; j < 4; j++) {
            __half2 th = __hfma2(wz, u2h(s3h[j]), u2h(r0h[j]));
            th = __hfma2(wy, u2h(s2h[j]), th);
            th = __hfma2(wx, u2h(s1h[j]), th);
            acc[j] = __hmax2(acc[j], __hmul2(u2h(pv[j]), th));
        }
    }

    float* orow = out + (size_t)row * COUT + c0;
    float2 f0 = __half22float2(acc[0]);
    float2 f1 = __half22float2(acc[1]);
    float2 f2 = __half22float2(acc[2]);
    float2 f3 = __half22float2(acc[3]);
    *(float4*)&orow[0] = make_float4(f0.x, f0.y, f1.x, f1.y);
    *(float4*)&orow[4] = make_float4(f2.x, f2.y, f3.x, f3.y);
}

extern "C" void kernel_launch(void* const* d_in, const int* in_sizes, int n_in,
                              void* d_out, int out_size) {
    const int*   idx   = (const int*)d_in[0];
    const float* verts = (const float*)d_in[1];
    const float* fmap  = (const float*)d_in[2];
    const float* dirs  = (const float*)d_in[3];
    const float* Wm    = (const float*)d_in[4];
    const float* bias  = (const float*)d_in[5];
    const float* gamma = (const float*)d_in[6];
    const float* beta  = (const float*)d_in[7];
    float* out = (float*)d_out;

    k_prep<<<PREP_GRID, 256>>>(fmap, Wm, idx);

    const int smem = 2 * 128 * SLD2 * (int)sizeof(__nv_bfloat16);   // 102400 B
    cudaFuncSetAttribute(k_gemm_mma, cudaFuncAttributeMaxDynamicSharedMemorySize, smem);
    k_gemm_mma<<<dim3(NROWS / 128, COUT / 128), 256, smem>>>(bias);

    k_norm<<<NROWS * COUT / 8 / 256, 256>>>(gamma, beta);
    k_final<<<NROWS / 4, 128>>>(idx, verts, dirs, out);
}

// round 13
// speedup vs baseline: 1.1209x; 1.0009x over previous
#include <cuda_runtime.h>
#include <cuda_bf16.h>
#include <cuda_fp16.h>
#include <cstdint>

#define BS   4
#define V    4096
#define NB   32
#define CIN  128
#define COUT 256
#define NROWS (BS*V)        // 16384 distinct (b,u) rows
#define NSAMP (BS*V*NB)     // 524288 samples for BN stats
#define KP    384           // logical split-K: A'=[hi|lo|hi], B'=[hi|hi|lo]
#define KST   256           // stored K: [hi|lo] only; GEMM remaps duplicate blocks
#define KHALF (KP/2)        // 192 per GEMM stage
#define SLD2  (KHALF + 8)   // padded smem stride (200 bf16 -> conflict-free ldmatrix)

// k_prep block-role partition (hist FIRST so it overlaps feat, not tails it)
#define NHIST_BLK 32        // 16384 samples/block, smem-privatized, sliced output
#define NPREPB_BLK 16       // 16 rows/block
#define NZERO_BLK 1
#define NFEAT_BLK 2048      // 8 rows/block (8 warps)
#define PREP_GRID (NHIST_BLK + NPREPB_BLK + NZERO_BLK + NFEAT_BLK)

// -------- scratch (device globals; no allocations allowed) --------
__device__ __align__(16) __nv_bfloat16 g_A2[NROWS * KST];  // 8.4 MB [hi|lo]
__device__ __align__(16) __nv_bfloat16 g_B2[COUT * KST];   // 128 KB [hi|lo]
__device__ __align__(16) __half g_Zh[NROWS * COUT];        // 8 MB  z -> relu(BN(z)) fp16
__device__ int   g_cnt8[8 * NROWS];                        // sliced histogram (no zeroing)
__device__ float g_sum[COUT], g_sq[COUT];

static __device__ __forceinline__ uint32_t smem_u32(const void* p) {
    uint32_t a;
    asm("{ .reg .u64 t; cvta.to.shared.u64 t, %1; cvt.u32.u64 %0, t; }"
        : "=r"(a) : "l"(p));
    return a;
}
static __device__ __forceinline__ void ldsm_x4(uint32_t* r, uint32_t addr) {
    asm volatile("ldmatrix.sync.aligned.m8n8.x4.shared.b16 {%0,%1,%2,%3}, [%4];"
                 : "=r"(r[0]), "=r"(r[1]), "=r"(r[2]), "=r"(r[3]) : "r"(addr));
}
static __device__ __forceinline__ void mma_bf16(float* c, const uint32_t* a,
                                                uint32_t b0, uint32_t b1) {
    asm volatile(
        "mma.sync.aligned.m16n8k16.row.col.f32.bf16.bf16.f32 "
        "{%0,%1,%2,%3}, {%4,%5,%6,%7}, {%8,%9}, {%0,%1,%2,%3};"
        : "+f"(c[0]), "+f"(c[1]), "+f"(c[2]), "+f"(c[3])
        : "r"(a[0]), "r"(a[1]), "r"(a[2]), "r"(a[3]), "r"(b0), "r"(b1));
}
static __device__ __forceinline__ uint32_t h2u(__half2 h) {
    return *reinterpret_cast<uint32_t*>(&h);
}
static __device__ __forceinline__ __half2 u2h(uint32_t u) {
    return *reinterpret_cast<__half2*>(&u);
}

// -------- K1: fused prep: hist (first!) + prepB + zero + feat ---------------
__global__ __launch_bounds__(256) void k_prep(const float* __restrict__ fmap,
                                              const float* __restrict__ Wm,
                                              const int* __restrict__ idx) {
    int blk = blockIdx.x;
    int tid = threadIdx.x;

    if (blk < NHIST_BLK) {
        // ---- hist: smem-privatized histogram, slice-private output (no atomics) ----
        __shared__ int scnt[V];
        int batch = blk >> 3, s = blk & 7;
        #pragma unroll
        for (int j = tid; j < V; j += 256) scnt[j] = 0;
        __syncthreads();
        const int4* src = (const int4*)(idx + (size_t)batch * (V * NB) + s * 16384);
        #pragma unroll 4
        for (int it = 0; it < 16; it++) {
            int4 v = src[it * 256 + tid];
            atomicAdd(&scnt[v.x], 1);
            atomicAdd(&scnt[v.y], 1);
            atomicAdd(&scnt[v.z], 1);
            atomicAdd(&scnt[v.w], 1);
        }
        __syncthreads();
        for (int j = tid; j < V; j += 256)
            g_cnt8[s * NROWS + (batch << 12) + j] = scnt[j];
    } else if (blk < NHIST_BLK + NPREPB_BLK) {
        // ---- prepB: B' rows = [hi(W) | lo(W)] (dup hi handled by GEMM remap) ----
        int base = (blk - NHIST_BLK) * 16;       // 16 rows per block
        for (int i = tid; i < 16 * CIN; i += 256) {
            int n = base + (i >> 7);
            int k = i & 127;
            float w = Wm[(size_t)n * CIN + k];
            __nv_bfloat16 h = __float2bfloat16_rn(w);
            __nv_bfloat16 l = __float2bfloat16_rn(w - __bfloat162float(h));
            __nv_bfloat16* dst = g_B2 + (size_t)n * KST;
            dst[k] = h; dst[k + 128] = l;
        }
    } else if (blk < NHIST_BLK + NPREPB_BLK + NZERO_BLK) {
        // ---- zero BN accumulators (replay-deterministic) ----
        g_sum[tid] = 0.0f;
        g_sq[tid]  = 0.0f;
    } else {
        // ---- feat: A' rows = [hi(F) | lo(F)], F = [fmap, ||fmap||] ----
        int warp = (blk - NHIST_BLK - NPREPB_BLK - NZERO_BLK) * 8 + (tid >> 5);
        int lane = tid & 31;
        const float* src = fmap + (size_t)warp * (CIN - 1);
        float v0 = src[lane];
        float v1 = src[lane + 32];
        float v2 = src[lane + 64];
        float v3 = (lane < 31) ? src[lane + 96] : 0.0f;
        float ss = v0*v0 + v1*v1 + v2*v2 + v3*v3;
        #pragma unroll
        for (int o = 16; o; o >>= 1) ss += __shfl_xor_sync(0xffffffffu, ss, o);
        if (lane == 31) v3 = sqrtf(ss);      // channel 127 = L2 distance
        __nv_bfloat16* dst = g_A2 + (size_t)warp * KST;
        float vv[4] = {v0, v1, v2, v3};
        #pragma unroll
        for (int q = 0; q < 4; q++) {
            int c = lane + q * 32;
            __nv_bfloat16 h = __float2bfloat16_rn(vv[q]);
            __nv_bfloat16 l = __float2bfloat16_rn(vv[q] - __bfloat162float(h));
            dst[c] = h; dst[c + 128] = l;
        }
    }
}

// -------- K2: HMMA GEMM  z = A' @ B'^T + bias -> fp16 Zh, fused BN stats ----
// CTA 128x128; logical K'=384 in TWO stages of 192 (smem 102 KB, 2 CTAs/SM).
// Gmem chunk remap reconstructs A'=[hi|lo|hi], B'=[hi|hi|lo] from [hi|lo].
__global__ __launch_bounds__(256, 2) void k_gemm_mma(const float* __restrict__ bias) {
    extern __shared__ __nv_bfloat16 sm[];
    __nv_bfloat16* As = sm;                  // [128][SLD2]
    __nv_bfloat16* Bs = sm + 128 * SLD2;     // [128][SLD2]
    int tid = threadIdx.x, wid = tid >> 5, lane = tid & 31;
    int mbase = blockIdx.x * 128, nbase = blockIdx.y * 128;

    int warp_m = (wid >> 2) * 64;            // 2 warp-rows
    int warp_n = (wid & 3) * 32;             // 4 warp-cols
    uint32_t sb = smem_u32(sm);
    uint32_t aaddr = sb + (uint32_t)(((warp_m + (lane & 15)) * SLD2 + (lane >> 4) * 8) * 2);
    uint32_t baddr = sb + (uint32_t)((128 * SLD2
                     + (warp_n + ((lane >> 4) & 1) * 8 + (lane & 7)) * SLD2
                     + ((lane >> 3) & 1) * 8) * 2);

    float acc[4][4][4];
    #pragma unroll
    for (int mi = 0; mi < 4; mi++)
        #pragma unroll
        for (int ni = 0; ni < 4; ni++)
            #pragma unroll
            for (int q = 0; q < 4; q++) acc[mi][ni][q] = 0.0f;

    #pragma unroll 1
    for (int s = 0; s < 2; s++) {
        if (s) __syncthreads();              // prior stage's mma reads complete
        const uint4* Ag = (const uint4*)(g_A2 + (size_t)mbase * KST);
        const uint4* Bg = (const uint4*)(g_B2 + (size_t)nbase * KST);
        #pragma unroll
        for (int i = tid; i < 128 * 24; i += 256) {
            int r = i / 24, c = i % 24;
            int g  = s * 24 + c;                   // logical k-chunk 0..47
            int ga = (g < 32) ? g : g - 32;        // A' = [hi|lo|hi]
            int gb = (g < 16) ? g : g - 16;        // B' = [hi|hi|lo]
            *(uint4*)&As[r * SLD2 + c * 8] = Ag[r * 32 + ga];  // 32 = KST/8 stride
            *(uint4*)&Bs[r * SLD2 + c * 8] = Bg[r * 32 + gb];
        }
        __syncthreads();

        #pragma unroll 2
        for (int ks = 0; ks < KHALF / 16; ks++) {
            uint32_t koff = (uint32_t)(ks * 16 * 2);
            uint32_t a[4][4], b[2][4];
            #pragma unroll
            for (int mi = 0; mi < 4; mi++)
                ldsm_x4(a[mi], aaddr + (uint32_t)(mi * 16 * SLD2 * 2) + koff);
            #pragma unroll
            for (int nj = 0; nj < 2; nj++)
                ldsm_x4(b[nj], baddr + (uint32_t)(nj * 16 * SLD2 * 2) + koff);
            #pragma unroll
            for (int mi = 0; mi < 4; mi++)
                #pragma unroll
                for (int ni = 0; ni < 4; ni++)
                    mma_bf16(acc[mi][ni], a[mi],
                             b[ni >> 1][(ni & 1) * 2], b[ni >> 1][(ni & 1) * 2 + 1]);
        }
    }

    // ---- epilogue: tiles dead; reuse smem for per-CTA stats ----
    __syncthreads();
    float* ssum = (float*)sm;        // [128]
    float* ssq  = ssum + 128;        // [128]
    if (tid < 128) ssum[tid] = 0.0f;
    else if (tid < 256) ssq[tid - 128] = 0.0f;
    __syncthreads();

    int r0 = lane >> 2, c0 = (lane & 3) * 2;
    float wlo[4], whi[4];
    #pragma unroll
    for (int mi = 0; mi < 4; mi++) {
        int rowA = mbase + warp_m + mi * 16 + r0;
        int lo = 0, hi = 0;
        #pragma unroll
        for (int s = 0; s < 8; s++) {
            lo += __ldg(&g_cnt8[s * NROWS + rowA]);
            hi += __ldg(&g_cnt8[s * NROWS + rowA + 8]);
        }
        wlo[mi] = (float)lo; whi[mi] = (float)hi;
    }
    #pragma unroll
    for (int ni = 0; ni < 4; ni++) {
        int coll = warp_n + ni * 8 + c0;             // 0..127 local col
        int col  = nbase + coll;
        float bx = __ldg(&bias[col]), by = __ldg(&bias[col + 1]);
        float sx = 0.f, qx = 0.f, sy = 0.f, qy = 0.f;
        #pragma unroll
        for (int mi = 0; mi < 4; mi++) {
            int rowA = mbase + warp_m + mi * 16 + r0;
            float v0 = acc[mi][ni][0] + bx, v1 = acc[mi][ni][1] + by;
            float v2 = acc[mi][ni][2] + bx, v3 = acc[mi][ni][3] + by;
            __half2 h0 = __floats2half2_rn(v0, v1);
            __half2 h1 = __floats2half2_rn(v2, v3);
            *(__half2*)&g_Zh[(size_t)rowA * COUT + col] = h0;
            *(__half2*)&g_Zh[(size_t)(rowA + 8) * COUT + col] = h1;
            sx = fmaf(wlo[mi], v0, sx); qx = fmaf(wlo[mi] * v0, v0, qx);
            sx = fmaf(whi[mi], v2, sx); qx = fmaf(whi[mi] * v2, v2, qx);
            sy = fmaf(wlo[mi], v1, sy); qy = fmaf(wlo[mi] * v1, v1, qy);
            sy = fmaf(whi[mi], v3, sy); qy = fmaf(whi[mi] * v3, v3, qy);
        }
        atomicAdd(&ssum[coll], sx);     atomicAdd(&ssq[coll], qx);
        atomicAdd(&ssum[coll + 1], sy); atomicAdd(&ssq[coll + 1], qy);
    }
    __syncthreads();
    if (tid < 128)      atomicAdd(&g_sum[nbase + tid], ssum[tid]);
    else if (tid < 256) atomicAdd(&g_sq[nbase + tid - 128], ssq[tid - 128]);
}

// -------- K3: Zh <- fp16(relu(BN(Zh))) in place, fp32 intermediate ----------
__global__ __launch_bounds__(256) void k_norm(const float* __restrict__ gamma,
                                              const float* __restrict__ beta) {
    __shared__ float sa[COUT], sd[COUT];
    int t = threadIdx.x;
    {
        const float invN = 1.0f / (float)NSAMP;
        float mean = g_sum[t] * invN;
        float var  = fmaxf(g_sq[t] * invN - mean * mean, 0.0f);
        float a    = gamma[t] / sqrtf(var + 1e-5f);
        sa[t] = a;
        sd[t] = beta[t] - mean * a;
    }
    __syncthreads();

    int i = blockIdx.x * 256 + t;            // uint4 index: 8 halves
    int c0 = (i * 8) & (COUT - 1);
    uint4 p = ((const uint4*)g_Zh)[i];
    uint32_t pv[4] = {p.x, p.y, p.z, p.w};
    #pragma unroll
    for (int j = 0; j < 4; j++) {
        float2 f = __half22float2(u2h(pv[j]));
        int c = c0 + j * 2;
        f.x = fmaxf(fmaf(f.x, sa[c],     sd[c]),     0.0f);
        f.y = fmaxf(fmaf(f.y, sa[c + 1], sd[c + 1]), 0.0f);
        pv[j] = h2u(__floats2half2_rn(f.x, f.y));
    }
    ((uint4*)g_Zh)[i] = make_uint4(pv[0], pv[1], pv[2], pv[3]);
}

// -------- K4: theta * zn, max over neighbors, half2 math --------------------
// 32 threads per row (one warp), 8 channels/thread; 4 rows per 128-thread block.
// theta relu dropped: zn >= 0 and acc starts at 0, so negative-theta candidates
// can never win the max — mathematically identical to relu(theta)*zn.
__global__ __launch_bounds__(128, 9) void k_final(const int* __restrict__ idx,
                                                  const float* __restrict__ verts,
                                                  const float* __restrict__ dirs,
                                                  float* __restrict__ out) {
    __shared__ uint4 sh[4][NB];      // per neighbor: wx2, wy2, wz2 (half2), byte-offset
    int r    = threadIdx.x >> 5;     // row within block
    int lane = threadIdx.x & 31;     // = neighbor id (setup) = channel group (main)
    int row  = blockIdx.x * 4 + r;
    int b    = row >> 12;

    // ---- setup: this warp fills its own row's neighbor table ----
    {
        int u = idx[(size_t)row * NB + lane];
        const float* nv = verts + (size_t)((b << 12) + u) * 3;
        const float* cv = verts + (size_t)row * 3;
        float dx = nv[0] - cv[0], dy = nv[1] - cv[1], dz = nv[2] - cv[2];
        float nrm = sqrtf(dx*dx + dy*dy + dz*dz);
        float inv = 1.0f / fmaxf(nrm, 1e-12f);
        uint4 w;
        w.x = h2u(__float2half2_rn(fmaf(dx*inv, 0.5f, 0.5f)));
        w.y = h2u(__float2half2_rn(fmaf(dy*inv, 0.5f, 0.5f)));
        w.z = h2u(__float2half2_rn(fmaf(dz*inv, 0.5f, 0.5f)));
        w.w = (uint32_t)(((b << 12) + u) * COUT * 2);   // byte offset into g_Zh
        sh[r][lane] = w;
    }

    // ---- per-thread channel constants (8 channels: c0..c0+7) ----
    int c0 = lane * 8;
    uint32_t s1h[4], s2h[4], s3h[4], r0h[4];
    #pragma unroll
    for (int j = 0; j < 4; j++) {
        int c = c0 + j * 2;
        float d0a = __ldg(&dirs[c]),            d0b = __ldg(&dirs[c + 1]);
        float d1a = __ldg(&dirs[COUT + c]),     d1b = __ldg(&dirs[COUT + c + 1]);
        float d2a = __ldg(&dirs[2*COUT + c]),   d2b = __ldg(&dirs[2*COUT + c + 1]);
        float d3a = __ldg(&dirs[3*COUT + c]),   d3b = __ldg(&dirs[3*COUT + c + 1]);
        r0h[j] = h2u(__floats2half2_rn(d0a, d0b));
        s1h[j] = h2u(__floats2half2_rn(d1a - d0a, d1b - d0b));
        s2h[j] = h2u(__floats2half2_rn(d2a - d0a, d2b - d0b));
        s3h[j] = h2u(__floats2half2_rn(d3a - d0a, d3b - d0b));
    }
    __syncwarp();

    const __half2 zero2 = __float2half2_rn(0.0f);
    __half2 acc[4] = {zero2, zero2, zero2, zero2};
    const char* zb = (const char*)g_Zh + (size_t)(lane * 16);

    #pragma unroll
    for (int n = 0; n < NB; n++) {
        uint4 w = sh[r][n];
        __half2 wx = u2h(w.x), wy = u2h(w.y), wz = u2h(w.z);
        uint4 p = *(const uint4*)(zb + w.w);
        uint32_t pv[4] = {p.x, p.y, p.z, p.w};
        #pragma unroll
        for (int j = 0; j < 4; j++) {
            __half2 th = __hfma2(wz, u2h(s3h[j]), u2h(r0h[j]));
            th = __hfma2(wy, u2h(s2h[j]), th);
            th = __hfma2(wx, u2h(s1h[j]), th);
            acc[j] = __hmax2(acc[j], __hmul2(u2h(pv[j]), th));
        }
    }

    float* orow = out + (size_t)row * COUT + c0;
    float2 f0 = __half22float2(acc[0]);
    float2 f1 = __half22float2(acc[1]);
    float2 f2 = __half22float2(acc[2]);
    float2 f3 = __half22float2(acc[3]);
    *(float4*)&orow[0] = make_float4(f0.x, f0.y, f1.x, f1.y);
    *(float4*)&orow[4] = make_float4(f2.x, f2.y, f3.x, f3.y);
}

extern "C" void kernel_launch(void* const* d_in, const int* in_sizes, int n_in,
                              void* d_out, int out_size) {
    const int*   idx   = (const int*)d_in[0];
    const float* verts = (const float*)d_in[1];
    const float* fmap  = (const float*)d_in[2];
    const float* dirs  = (const float*)d_in[3];
    const float* Wm    = (const float*)d_in[4];
    const float* bias  = (const float*)d_in[5];
    const float* gamma = (const float*)d_in[6];
    const float* beta  = (const float*)d_in[7];
    float* out = (float*)d_out;

    k_prep<<<PREP_GRID, 256>>>(fmap, Wm, idx);

    const int smem = 2 * 128 * SLD2 * (int)sizeof(__nv_bfloat16);   // 102400 B
    cudaFuncSetAttribute(k_gemm_mma, cudaFuncAttributeMaxDynamicSharedMemorySize, smem);
    k_gemm_mma<<<dim3(NROWS / 128, COUT / 128), 256, smem>>>(bias);

    k_norm<<<NROWS * COUT / 8 / 256, 256>>>(gamma, beta);
    k_final<<<NROWS / 4, 128>>>(idx, verts, dirs, out);
}

// round 14
// speedup vs baseline: 1.2522x; 1.1171x over previous
#include <cuda_runtime.h>
#include <cuda_bf16.h>
#include <cuda_fp16.h>
#include <cstdint>

#define BS   4
#define V    4096
#define NB   32
#define CIN  128
#define COUT 256
#define NROWS (BS*V)        // 16384 distinct (b,u) rows
#define NSAMP (BS*V*NB)     // 524288 samples for BN stats
#define KK    128           // GEMM K (plain fp16, fp32 accum)
#define SLDG  (KK + 8)      // padded smem stride (136 halves -> conflict-free ldmatrix)

// k_prep block-role partition (hist FIRST so it overlaps feat, not tails it)
#define NHIST_BLK 64        // 8192 samples/block, smem-privatized, sliced output
#define NSLICE 16
#define NPREPB_BLK 16       // 16 rows/block
#define NZERO_BLK 1
#define NFEAT_BLK 2048      // 8 rows/block (8 warps)
#define PREP_GRID (NHIST_BLK + NPREPB_BLK + NZERO_BLK + NFEAT_BLK)

// -------- scratch (device globals; no allocations allowed) --------
__device__ __align__(16) __half g_A2[NROWS * KK];          // 4 MB   fp16 F
__device__ __align__(16) __half g_B2[COUT * KK];           // 64 KB  fp16 W
__device__ __align__(16) __half g_Zh[NROWS * COUT];        // 8 MB   z -> relu(BN(z))
__device__ int   g_cnt16[NSLICE * NROWS];                  // sliced histogram
__device__ float g_sum[COUT], g_sq[COUT];

static __device__ __forceinline__ uint32_t smem_u32(const void* p) {
    uint32_t a;
    asm("{ .reg .u64 t; cvta.to.shared.u64 t, %1; cvt.u32.u64 %0, t; }"
        : "=r"(a) : "l"(p));
    return a;
}
static __device__ __forceinline__ void ldsm_x4(uint32_t* r, uint32_t addr) {
    asm volatile("ldmatrix.sync.aligned.m8n8.x4.shared.b16 {%0,%1,%2,%3}, [%4];"
                 : "=r"(r[0]), "=r"(r[1]), "=r"(r[2]), "=r"(r[3]) : "r"(addr));
}
static __device__ __forceinline__ void mma_f16(float* c, const uint32_t* a,
                                               uint32_t b0, uint32_t b1) {
    asm volatile(
        "mma.sync.aligned.m16n8k16.row.col.f32.f16.f16.f32 "
        "{%0,%1,%2,%3}, {%4,%5,%6,%7}, {%8,%9}, {%0,%1,%2,%3};"
        : "+f"(c[0]), "+f"(c[1]), "+f"(c[2]), "+f"(c[3])
        : "r"(a[0]), "r"(a[1]), "r"(a[2]), "r"(a[3]), "r"(b0), "r"(b1));
}
static __device__ __forceinline__ uint32_t h2u(__half2 h) {
    return *reinterpret_cast<uint32_t*>(&h);
}
static __device__ __forceinline__ __half2 u2h(uint32_t u) {
    return *reinterpret_cast<__half2*>(&u);
}

// -------- K1: fused prep: hist (first!) + prepB + zero + feat ---------------
__global__ __launch_bounds__(256) void k_prep(const float* __restrict__ fmap,
                                              const float* __restrict__ Wm,
                                              const int* __restrict__ idx) {
    int blk = blockIdx.x;
    int tid = threadIdx.x;

    if (blk < NHIST_BLK) {
        // ---- hist: smem-privatized histogram, slice-private output (no atomics) ----
        __shared__ int scnt[V];
        int batch = blk >> 4, s = blk & 15;
        #pragma unroll
        for (int j = tid; j < V; j += 256) scnt[j] = 0;
        __syncthreads();
        const int4* src = (const int4*)(idx + (size_t)batch * (V * NB) + s * 8192);
        #pragma unroll 4
        for (int it = 0; it < 8; it++) {
            int4 v = src[it * 256 + tid];
            atomicAdd(&scnt[v.x], 1);
            atomicAdd(&scnt[v.y], 1);
            atomicAdd(&scnt[v.z], 1);
            atomicAdd(&scnt[v.w], 1);
        }
        __syncthreads();
        for (int j = tid; j < V; j += 256)
            g_cnt16[s * NROWS + (batch << 12) + j] = scnt[j];
    } else if (blk < NHIST_BLK + NPREPB_BLK) {
        // ---- prepB: fp16 W rows ----
        int base = (blk - NHIST_BLK) * 16;       // 16 rows per block
        for (int i = tid; i < 16 * CIN; i += 256) {
            int n = base + (i >> 7);
            int k = i & 127;
            g_B2[(size_t)n * KK + k] = __float2half_rn(Wm[(size_t)n * CIN + k]);
        }
    } else if (blk < NHIST_BLK + NPREPB_BLK + NZERO_BLK) {
        // ---- zero BN accumulators (replay-deterministic) ----
        g_sum[tid] = 0.0f;
        g_sq[tid]  = 0.0f;
    } else {
        // ---- feat: fp16 F rows = [fmap, ||fmap||] ----
        int warp = (blk - NHIST_BLK - NPREPB_BLK - NZERO_BLK) * 8 + (tid >> 5);
        int lane = tid & 31;
        const float* src = fmap + (size_t)warp * (CIN - 1);
        float v0 = src[lane];
        float v1 = src[lane + 32];
        float v2 = src[lane + 64];
        float v3 = (lane < 31) ? src[lane + 96] : 0.0f;
        float ss = v0*v0 + v1*v1 + v2*v2 + v3*v3;
        #pragma unroll
        for (int o = 16; o; o >>= 1) ss += __shfl_xor_sync(0xffffffffu, ss, o);
        if (lane == 31) v3 = sqrtf(ss);      // channel 127 = L2 distance
        __half* dst = g_A2 + (size_t)warp * KK;
        dst[lane]      = __float2half_rn(v0);
        dst[lane + 32] = __float2half_rn(v1);
        dst[lane + 64] = __float2half_rn(v2);
        dst[lane + 96] = __float2half_rn(v3);
    }
}

// -------- K2: HMMA GEMM  z = F @ W^T + bias -> fp16 Zh, fused BN stats ------
// CTA 128x128, K=128 resident (smem 68 KB -> 2 CTAs/SM, single wave).
__global__ __launch_bounds__(256, 2) void k_gemm_mma(const float* __restrict__ bias) {
    extern __shared__ __half sm[];
    __half* As = sm;                  // [128][SLDG]
    __half* Bs = sm + 128 * SLDG;     // [128][SLDG]
    int tid = threadIdx.x, wid = tid >> 5, lane = tid & 31;
    int mbase = blockIdx.x * 128, nbase = blockIdx.y * 128;

    // cooperative tile load (uint4 = 8 halves), 16 chunks/row
    {
        const uint4* Ag = (const uint4*)(g_A2 + (size_t)mbase * KK);
        const uint4* Bg = (const uint4*)(g_B2 + (size_t)nbase * KK);
        #pragma unroll
        for (int i = tid; i < 128 * 16; i += 256) {
            int r = i >> 4, c = i & 15;
            *(uint4*)&As[r * SLDG + c * 8] = Ag[r * 16 + c];
            *(uint4*)&Bs[r * SLDG + c * 8] = Bg[r * 16 + c];
        }
    }
    __syncthreads();

    int warp_m = (wid >> 2) * 64;            // 2 warp-rows
    int warp_n = (wid & 3) * 32;             // 4 warp-cols
    uint32_t sb = smem_u32(sm);
    uint32_t aaddr = sb + (uint32_t)(((warp_m + (lane & 15)) * SLDG + (lane >> 4) * 8) * 2);
    uint32_t baddr = sb + (uint32_t)((128 * SLDG
                     + (warp_n + ((lane >> 4) & 1) * 8 + (lane & 7)) * SLDG
                     + ((lane >> 3) & 1) * 8) * 2);

    float acc[4][4][4];
    #pragma unroll
    for (int mi = 0; mi < 4; mi++)
        #pragma unroll
        for (int ni = 0; ni < 4; ni++)
            #pragma unroll
            for (int q = 0; q < 4; q++) acc[mi][ni][q] = 0.0f;

    #pragma unroll 2
    for (int ks = 0; ks < KK / 16; ks++) {
        uint32_t koff = (uint32_t)(ks * 16 * 2);
        uint32_t a[4][4], b[2][4];
        #pragma unroll
        for (int mi = 0; mi < 4; mi++)
            ldsm_x4(a[mi], aaddr + (uint32_t)(mi * 16 * SLDG * 2) + koff);
        #pragma unroll
        for (int nj = 0; nj < 2; nj++)
            ldsm_x4(b[nj], baddr + (uint32_t)(nj * 16 * SLDG * 2) + koff);
        #pragma unroll
        for (int mi = 0; mi < 4; mi++)
            #pragma unroll
            for (int ni = 0; ni < 4; ni++)
                mma_f16(acc[mi][ni], a[mi],
                        b[ni >> 1][(ni & 1) * 2], b[ni >> 1][(ni & 1) * 2 + 1]);
    }

    // ---- epilogue: tiles dead; reuse smem for per-CTA stats ----
    __syncthreads();
    float* ssum = (float*)sm;        // [128]
    float* ssq  = ssum + 128;        // [128]
    if (tid < 128) ssum[tid] = 0.0f;
    else if (tid < 256) ssq[tid - 128] = 0.0f;
    __syncthreads();

    int r0 = lane >> 2, c0 = (lane & 3) * 2;
    float wlo[4], whi[4];
    #pragma unroll
    for (int mi = 0; mi < 4; mi++) {
        int rowA = mbase + warp_m + mi * 16 + r0;
        int lo = 0, hi = 0;
        #pragma unroll
        for (int s = 0; s < NSLICE; s++) {
            lo += __ldg(&g_cnt16[s * NROWS + rowA]);
            hi += __ldg(&g_cnt16[s * NROWS + rowA + 8]);
        }
        wlo[mi] = (float)lo; whi[mi] = (float)hi;
    }
    #pragma unroll
    for (int ni = 0; ni < 4; ni++) {
        int coll = warp_n + ni * 8 + c0;             // 0..127 local col
        int col  = nbase + coll;
        float bx = __ldg(&bias[col]), by = __ldg(&bias[col + 1]);
        float sx = 0.f, qx = 0.f, sy = 0.f, qy = 0.f;
        #pragma unroll
        for (int mi = 0; mi < 4; mi++) {
            int rowA = mbase + warp_m + mi * 16 + r0;
            float v0 = acc[mi][ni][0] + bx, v1 = acc[mi][ni][1] + by;
            float v2 = acc[mi][ni][2] + bx, v3 = acc[mi][ni][3] + by;
            __half2 h0 = __floats2half2_rn(v0, v1);
            __half2 h1 = __floats2half2_rn(v2, v3);
            *(__half2*)&g_Zh[(size_t)rowA * COUT + col] = h0;
            *(__half2*)&g_Zh[(size_t)(rowA + 8) * COUT + col] = h1;
            sx = fmaf(wlo[mi], v0, sx); qx = fmaf(wlo[mi] * v0, v0, qx);
            sx = fmaf(whi[mi], v2, sx); qx = fmaf(whi[mi] * v2, v2, qx);
            sy = fmaf(wlo[mi], v1, sy); qy = fmaf(wlo[mi] * v1, v1, qy);
            sy = fmaf(whi[mi], v3, sy); qy = fmaf(whi[mi] * v3, v3, qy);
        }
        atomicAdd(&ssum[coll], sx);     atomicAdd(&ssq[coll], qx);
        atomicAdd(&ssum[coll + 1], sy); atomicAdd(&ssq[coll + 1], qy);
    }
    __syncthreads();
    if (tid < 128)      atomicAdd(&g_sum[nbase + tid], ssum[tid]);
    else if (tid < 256) atomicAdd(&g_sq[nbase + tid - 128], ssq[tid - 128]);
}

// -------- K3: Zh <- fp16(relu(BN(Zh))) in place, fp32 intermediate ----------
__global__ __launch_bounds__(256) void k_norm(const float* __restrict__ gamma,
                                              const float* __restrict__ beta) {
    __shared__ float sa[COUT], sd[COUT];
    int t = threadIdx.x;
    {
        const float invN = 1.0f / (float)NSAMP;
        float mean = g_sum[t] * invN;
        float var  = fmaxf(g_sq[t] * invN - mean * mean, 0.0f);
        float a    = gamma[t] / sqrtf(var + 1e-5f);
        sa[t] = a;
        sd[t] = beta[t] - mean * a;
    }
    __syncthreads();

    int i = blockIdx.x * 256 + t;            // uint4 index: 8 halves
    int c0 = (i * 8) & (COUT - 1);
    uint4 p = ((const uint4*)g_Zh)[i];
    uint32_t pv[4] = {p.x, p.y, p.z, p.w};
    #pragma unroll
    for (int j = 0; j < 4; j++) {
        float2 f = __half22float2(u2h(pv[j]));
        int c = c0 + j * 2;
        f.x = fmaxf(fmaf(f.x, sa[c],     sd[c]),     0.0f);
        f.y = fmaxf(fmaf(f.y, sa[c + 1], sd[c + 1]), 0.0f);
        pv[j] = h2u(__floats2half2_rn(f.x, f.y));
    }
    ((uint4*)g_Zh)[i] = make_uint4(pv[0], pv[1], pv[2], pv[3]);
}

// -------- K4: theta * zn, max over neighbors, half2 math --------------------
// 32 threads per row (one warp), 8 channels/thread; 4 rows per 128-thread block.
// theta relu dropped: zn >= 0 and acc starts at 0, so negative-theta candidates
// can never win the max — mathematically identical to relu(theta)*zn.
__global__ __launch_bounds__(128, 9) void k_final(const int* __restrict__ idx,
                                                  const float* __restrict__ verts,
                                                  const float* __restrict__ dirs,
                                                  float* __restrict__ out) {
    __shared__ uint4 sh[4][NB];      // per neighbor: wx2, wy2, wz2 (half2), byte-offset
    int r    = threadIdx.x >> 5;     // row within block
    int lane = threadIdx.x & 31;     // = neighbor id (setup) = channel group (main)
    int row  = blockIdx.x * 4 + r;
    int b    = row >> 12;

    // ---- setup: this warp fills its own row's neighbor table ----
    {
        int u = idx[(size_t)row * NB + lane];
        const float* nv = verts + (size_t)((b << 12) + u) * 3;
        const float* cv = verts + (size_t)row * 3;
        float dx = nv[0] - cv[0], dy = nv[1] - cv[1], dz = nv[2] - cv[2];
        float nrm = sqrtf(dx*dx + dy*dy + dz*dz);
        float inv = 1.0f / fmaxf(nrm, 1e-12f);
        uint4 w;
        w.x = h2u(__float2half2_rn(fmaf(dx*inv, 0.5f, 0.5f)));
        w.y = h2u(__float2half2_rn(fmaf(dy*inv, 0.5f, 0.5f)));
        w.z = h2u(__float2half2_rn(fmaf(dz*inv, 0.5f, 0.5f)));
        w.w = (uint32_t)(((b << 12) + u) * COUT * 2);   // byte offset into g_Zh
        sh[r][lane] = w;
    }

    // ---- per-thread channel constants (8 channels: c0..c0+7) ----
    int c0 = lane * 8;
    uint32_t s1h[4], s2h[4], s3h[4], r0h[4];
    #pragma unroll
    for (int j = 0; j < 4; j++) {
        int c = c0 + j * 2;
        float d0a = __ldg(&dirs[c]),            d0b = __ldg(&dirs[c + 1]);
        float d1a = __ldg(&dirs[COUT + c]),     d1b = __ldg(&dirs[COUT + c + 1]);
        float d2a = __ldg(&dirs[2*COUT + c]),   d2b = __ldg(&dirs[2*COUT + c + 1]);
        float d3a = __ldg(&dirs[3*COUT + c]),   d3b = __ldg(&dirs[3*COUT + c + 1]);
        r0h[j] = h2u(__floats2half2_rn(d0a, d0b));
        s1h[j] = h2u(__floats2half2_rn(d1a - d0a, d1b - d0b));
        s2h[j] = h2u(__floats2half2_rn(d2a - d0a, d2b - d0b));
        s3h[j] = h2u(__floats2half2_rn(d3a - d0a, d3b - d0b));
    }
    __syncwarp();

    const __half2 zero2 = __float2half2_rn(0.0f);
    __half2 acc[4] = {zero2, zero2, zero2, zero2};
    const char* zb = (const char*)g_Zh + (size_t)(lane * 16);

    #pragma unroll
    for (int n = 0; n < NB; n++) {
        uint4 w = sh[r][n];
        __half2 wx = u2h(w.x), wy = u2h(w.y), wz = u2h(w.z);
        uint4 p = *(const uint4*)(zb + w.w);
        uint32_t pv[4] = {p.x, p.y, p.z, p.w};
        #pragma unroll
        for (int j = 0; j < 4; j++) {
            __half2 th = __hfma2(wz, u2h(s3h[j]), u2h(r0h[j]));
            th = __hfma2(wy, u2h(s2h[j]), th);
            th = __hfma2(wx, u2h(s1h[j]), th);
            acc[j] = __hmax2(acc[j], __hmul2(u2h(pv[j]), th));
        }
    }

    float* orow = out + (size_t)row * COUT + c0;
    float2 f0 = __half22float2(acc[0]);
    float2 f1 = __half22float2(acc[1]);
    float2 f2 = __half22float2(acc[2]);
    float2 f3 = __half22float2(acc[3]);
    *(float4*)&orow[0] = make_float4(f0.x, f0.y, f1.x, f1.y);
    *(float4*)&orow[4] = make_float4(f2.x, f2.y, f3.x, f3.y);
}

extern "C" void kernel_launch(void* const* d_in, const int* in_sizes, int n_in,
                              void* d_out, int out_size) {
    const int*   idx   = (const int*)d_in[0];
    const float* verts = (const float*)d_in[1];
    const float* fmap  = (const float*)d_in[2];
    const float* dirs  = (const float*)d_in[3];
    const float* Wm    = (const float*)d_in[4];
    const float* bias  = (const float*)d_in[5];
    const float* gamma = (const float*)d_in[6];
    const float* beta  = (const float*)d_in[7];
    float* out = (float*)d_out;

    k_prep<<<PREP_GRID, 256>>>(fmap, Wm, idx);

    const int smem = 2 * 128 * SLDG * (int)sizeof(__half);   // 69632 B
    cudaFuncSetAttribute(k_gemm_mma, cudaFuncAttributeMaxDynamicSharedMemorySize, smem);
    k_gemm_mma<<<dim3(NROWS / 128, COUT / 128), 256, smem>>>(bias);

    k_norm<<<NROWS * COUT / 8 / 256, 256>>>(gamma, beta);
    k_final<<<NROWS / 4, 128>>>(idx, verts, dirs, out);
}